// round 12
// baseline (speedup 1.0000x reference)
#include <cuda_runtime.h>
#include <cuda_fp16.h>
#include <mma.h>

using namespace nvcuda;

#define NN 100000
#define EE 1600000
#define EQ 400000   // EE/4
#define MD 128      // padded bucket capacity (P(deg>=128 | Poisson(16)) ~ e^-150)

// ---------------- scratch (static device globals; no allocation) ----------------
__device__ int    g_deg[NN];          // zero-init at load; re-zeroed by k_agg32 each call
__device__ int    g_col[NN * MD];     // padded CSR buckets
__device__ __half g_h16[NN * 64];
__device__ __half g_act16[NN * 64];
__device__ float  g_adst[NN * 8];
__device__ float  g_asrc[NN * 8];

// dtype sniff: int64 indices in range -> is64 (8 loads from one cached line)
__device__ __forceinline__ int sniff64(const long long* p64) {
    int is64 = 1;
#pragma unroll
    for (int k = 0; k < 8; k++) {
        long long v = p64[k];
        if (v < 0 || v >= NN) is64 = 0;
    }
    return is64;
}

// ---------------- one-pass padded-CSR build ----------------
// t < EQ: 4 edges/thread (skip original self-loops; exp(-1e9-amax)==0 in reference).
// t >= EQ: append self-loop for node t-EQ.
__global__ void k_build(const void* ei) {
    int t = blockIdx.x * blockDim.x + threadIdx.x;
    if (t < EQ) {
        const long long* p64 = (const long long*)ei;
        int is64 = sniff64(p64);
        int e0 = t * 4;
        int s[4], d[4];
        if (is64) {
#pragma unroll
            for (int j = 0; j < 4; j++) {
                s[j] = (int)p64[e0 + j];
                d[j] = (int)p64[EE + e0 + j];
            }
        } else {
            const int* p = (const int*)ei;
#pragma unroll
            for (int j = 0; j < 4; j++) {
                s[j] = p[e0 + j];
                d[j] = p[EE + e0 + j];
            }
        }
        int pos[4];
#pragma unroll
        for (int j = 0; j < 4; j++)
            pos[j] = (s[j] != d[j]) ? atomicAdd(&g_deg[d[j]], 1) : -1;
#pragma unroll
        for (int j = 0; j < 4; j++)
            if (pos[j] >= 0 && pos[j] < MD) g_col[(d[j] << 7) + pos[j]] = s[j];
    } else {
        int n = t - EQ;
        if (n < NN) {
            int pos = atomicAdd(&g_deg[n], 1);
            if (pos < MD) g_col[(n << 7) + pos] = n;  // appended self-loop
        }
    }
}

// ---------------- wmma tensor-core GEMM + fused attention-dot epilogue ----------------
template <int K, int NOUT, int HEADS, bool HALF_A>
__global__ __launch_bounds__(256) void k_gemm_wmma(const float* __restrict__ Af,
                                                   const float* __restrict__ W,
                                                   const float* __restrict__ att) {
    constexpr int LDA = K + 8;
    constexpr int LDB = NOUT + 8;
    constexpr int LDC = NOUT + 8;
    constexpr int AB_BYTES = 64 * LDA * 2 + K * LDB * 2;
    constexpr int C_BYTES = 64 * LDC * 4;
    constexpr int SM_BYTES = AB_BYTES > C_BYTES ? AB_BYTES : C_BYTES;
    __shared__ __align__(16) char smem[SM_BYTES];
    __half (*Asm)[LDA] = reinterpret_cast<__half (*)[LDA]>(smem);
    __half (*Bsm)[LDB] = reinterpret_cast<__half (*)[LDB]>(smem + 64 * LDA * 2);
    float  (*Csm)[LDC] = reinterpret_cast<float (*)[LDC]>(smem);

    int tid = threadIdx.x;
    int w = tid >> 5;
    int row0 = blockIdx.x * 64;

    for (int i = tid; i < K * NOUT / 4; i += 256) {
        int r = i / (NOUT / 4), c4 = i % (NOUT / 4);
        float4 v = ((const float4*)W)[i];
        __half2* dst = (__half2*)&Bsm[r][c4 * 4];
        dst[0] = __floats2half2_rn(v.x, v.y);
        dst[1] = __floats2half2_rn(v.z, v.w);
    }
    if (HALF_A) {
        for (int i = tid; i < 64 * K / 8; i += 256) {
            int r = i / (K / 8), c8 = i % (K / 8);
            float4 v = make_float4(0.f, 0.f, 0.f, 0.f);
            if (row0 + r < NN)
                v = *(const float4*)&g_act16[(row0 + r) * K + c8 * 8];
            *(float4*)&Asm[r][c8 * 8] = v;
        }
    } else {
        for (int i = tid; i < 64 * K / 4; i += 256) {
            int r = i / (K / 4), c4 = i % (K / 4);
            float4 v = make_float4(0.f, 0.f, 0.f, 0.f);
            if (row0 + r < NN)
                v = *(const float4*)&Af[(row0 + r) * K + c4 * 4];
            __half2* dst = (__half2*)&Asm[r][c4 * 4];
            dst[0] = __floats2half2_rn(v.x, v.y);
            dst[1] = __floats2half2_rn(v.z, v.w);
        }
    }
    __syncthreads();

    constexpr int CFRAGS = NOUT / 32;
    int rb = (w >> 1) * 16;
    int col0 = (w & 1) * (NOUT / 2);

    wmma::fragment<wmma::accumulator, 16, 16, 16, float> cfrag[CFRAGS];
#pragma unroll
    for (int j = 0; j < CFRAGS; j++) wmma::fill_fragment(cfrag[j], 0.f);

#pragma unroll
    for (int kk = 0; kk < K / 16; kk++) {
        wmma::fragment<wmma::matrix_a, 16, 16, 16, __half, wmma::row_major> afrag;
        wmma::load_matrix_sync(afrag, &Asm[rb][kk * 16], LDA);
#pragma unroll
        for (int j = 0; j < CFRAGS; j++) {
            wmma::fragment<wmma::matrix_b, 16, 16, 16, __half, wmma::row_major> bfrag;
            wmma::load_matrix_sync(bfrag, &Bsm[kk * 16][col0 + 16 * j], LDB);
            wmma::mma_sync(cfrag[j], afrag, bfrag, cfrag[j]);
        }
    }
    __syncthreads();
#pragma unroll
    for (int j = 0; j < CFRAGS; j++)
        wmma::store_matrix_sync(&Csm[rb][col0 + 16 * j], cfrag[j], LDC, wmma::mem_row_major);
    __syncthreads();

    for (int i = tid; i < 64 * NOUT / 2; i += 256) {
        int r = i / (NOUT / 2), c2 = i % (NOUT / 2);
        if (row0 + r < NN)
            *(__half2*)&g_h16[(row0 + r) * NOUT + c2 * 2] =
                __floats2half2_rn(Csm[r][c2 * 2], Csm[r][c2 * 2 + 1]);
    }
    constexpr int CPH = NOUT / HEADS;
    for (int idx = tid; idx < 64 * HEADS; idx += 256) {
        int r = idx / HEADS, h = idx % HEADS;
        float sd = 0.f, ss = 0.f;
#pragma unroll
        for (int c = 0; c < CPH; c++) {
            float v = Csm[r][h * CPH + c];
            sd += v * att[h * (2 * CPH) + c];
            ss += v * att[h * (2 * CPH) + CPH + c];
        }
        int row = row0 + r;
        if (row < NN) {
            g_adst[row * HEADS + h] = sd;
            g_asrc[row * HEADS + h] = ss;
        }
    }
}

__device__ __forceinline__ float leaky_exp(float a) {
    a = a > 0.f ? a : 0.2f * a;
    return __expf(a);
}

// ---------------- aggregate H=8: warp per node, 8-edge batches ----------------
__global__ __launch_bounds__(256) void k_agg8(const float* __restrict__ bias, int do_elu) {
    int t = blockIdx.x * blockDim.x + threadIdx.x;
    int n = t >> 5, lane = t & 31;
    if (n >= NN) return;
    const unsigned full = 0xffffffffu;
    int start = n << 7;
    int end = start + min(g_deg[n], MD);
    int hA = lane & 7;
    int hB = lane >> 2;
    int eoff = lane >> 3;

    float adstA = g_adst[n * 8 + hA];
    float2 acc = make_float2(0.f, 0.f);
    float dsum = 0.f;

    for (int base = start; base < end; base += 8) {
        int eA = base + eoff;
        int eB = eA + 4;
        int validA = eA < end;
        int validB = eB < end;
        int ecA = validA ? eA : end - 1;
        int ecB = validB ? eB : end - 1;
        int sA = g_col[ecA];
        int sB = g_col[ecB];
        float aA = g_asrc[sA * 8 + hA];
        float aB = g_asrc[sB * 8 + hA];

        int s0 = __shfl_sync(full, sA, 0);
        int s1 = __shfl_sync(full, sA, 8);
        int s2 = __shfl_sync(full, sA, 16);
        int s3 = __shfl_sync(full, sA, 24);
        int s4 = __shfl_sync(full, sB, 0);
        int s5 = __shfl_sync(full, sB, 8);
        int s6 = __shfl_sync(full, sB, 16);
        int s7 = __shfl_sync(full, sB, 24);
        float2 v0 = __half22float2(*(const __half2*)&g_h16[s0 * 64 + lane * 2]);
        float2 v1 = __half22float2(*(const __half2*)&g_h16[s1 * 64 + lane * 2]);
        float2 v2 = __half22float2(*(const __half2*)&g_h16[s2 * 64 + lane * 2]);
        float2 v3 = __half22float2(*(const __half2*)&g_h16[s3 * 64 + lane * 2]);
        float2 v4 = __half22float2(*(const __half2*)&g_h16[s4 * 64 + lane * 2]);
        float2 v5 = __half22float2(*(const __half2*)&g_h16[s5 * 64 + lane * 2]);
        float2 v6 = __half22float2(*(const __half2*)&g_h16[s6 * 64 + lane * 2]);
        float2 v7 = __half22float2(*(const __half2*)&g_h16[s7 * 64 + lane * 2]);

        float exA = leaky_exp(adstA + aA);
        float exB = leaky_exp(adstA + aB);
        exA = validA ? exA : 0.f;
        exB = validB ? exB : 0.f;

        float w0 = __shfl_sync(full, exA, hB);
        float w1 = __shfl_sync(full, exA, 8 + hB);
        float w2 = __shfl_sync(full, exA, 16 + hB);
        float w3 = __shfl_sync(full, exA, 24 + hB);
        float w4 = __shfl_sync(full, exB, hB);
        float w5 = __shfl_sync(full, exB, 8 + hB);
        float w6 = __shfl_sync(full, exB, 16 + hB);
        float w7 = __shfl_sync(full, exB, 24 + hB);

        acc.x += v0.x * w0 + v1.x * w1 + v2.x * w2 + v3.x * w3;
        acc.x += v4.x * w4 + v5.x * w5 + v6.x * w6 + v7.x * w7;
        acc.y += v0.y * w0 + v1.y * w1 + v2.y * w2 + v3.y * w3;
        acc.y += v4.y * w4 + v5.y * w5 + v6.y * w6 + v7.y * w7;
        dsum += ((w0 + w1) + (w2 + w3)) + ((w4 + w5) + (w6 + w7));
    }
    float inv = 1.f / dsum;
    float o0 = acc.x * inv + bias[lane * 2];
    float o1 = acc.y * inv + bias[lane * 2 + 1];
    if (do_elu) {
        o0 = o0 > 0.f ? o0 : expm1f(o0);
        o1 = o1 > 0.f ? o1 : expm1f(o1);
    }
    *(__half2*)&g_act16[n * 64 + lane * 2] = __floats2half2_rn(o0, o1);
}

// ---------------- aggregate H=1: warp per node, 8-edge batches; resets g_deg ----------------
__global__ __launch_bounds__(256) void k_agg32(const float* __restrict__ bias,
                                               float* __restrict__ outp) {
    int t = blockIdx.x * blockDim.x + threadIdx.x;
    int n = t >> 5, lane = t & 31;
    if (n >= NN) return;
    const unsigned full = 0xffffffffu;
    int start = n << 7;
    int end = start + min(g_deg[n], MD);
    if (lane == 0) g_deg[n] = 0;  // reset for next call (this warp is sole reader of deg[n])
    int half = lane >> 4;
    int c2 = (lane & 15) * 2;
    int eoff = lane & 7;

    float adst = g_adst[n];
    float2 acc = make_float2(0.f, 0.f);
    float dsum = 0.f;

    for (int base = start; base < end; base += 8) {
        int e = base + eoff;
        int valid = e < end;
        int ec = valid ? e : end - 1;
        int scol = g_col[ec];
        float ex = leaky_exp(adst + g_asrc[scol]);
        ex = valid ? ex : 0.f;

        int i0 = half, i1 = 2 + half, i2 = 4 + half, i3 = 6 + half;
        int s0 = __shfl_sync(full, scol, i0);
        int s1 = __shfl_sync(full, scol, i1);
        int s2 = __shfl_sync(full, scol, i2);
        int s3 = __shfl_sync(full, scol, i3);
        float2 v0 = __half22float2(*(const __half2*)&g_h16[s0 * 32 + c2]);
        float2 v1 = __half22float2(*(const __half2*)&g_h16[s1 * 32 + c2]);
        float2 v2 = __half22float2(*(const __half2*)&g_h16[s2 * 32 + c2]);
        float2 v3 = __half22float2(*(const __half2*)&g_h16[s3 * 32 + c2]);
        float w0 = __shfl_sync(full, ex, i0);
        float w1 = __shfl_sync(full, ex, i1);
        float w2 = __shfl_sync(full, ex, i2);
        float w3 = __shfl_sync(full, ex, i3);

        acc.x += v0.x * w0 + v1.x * w1 + v2.x * w2 + v3.x * w3;
        acc.y += v0.y * w0 + v1.y * w1 + v2.y * w2 + v3.y * w3;
        dsum += (w0 + w1) + (w2 + w3);
    }
    acc.x += __shfl_xor_sync(full, acc.x, 16);
    acc.y += __shfl_xor_sync(full, acc.y, 16);
    dsum += __shfl_xor_sync(full, dsum, 16);
    if (lane < 16) {
        float inv = 1.f / dsum;
        outp[n * 32 + c2] = acc.x * inv + bias[c2];
        outp[n * 32 + c2 + 1] = acc.y * inv + bias[c2 + 1];
    }
}

// ---------------- launch ----------------
extern "C" void kernel_launch(void* const* d_in, const int* in_sizes, int n_in,
                              void* d_out, int out_size) {
    const float* x    = (const float*)d_in[0];
    const void*  ei   = d_in[1];
    const float* W1   = (const float*)d_in[2];
    const float* att1 = (const float*)d_in[3];
    const float* b1   = (const float*)d_in[4];
    const float* W2   = (const float*)d_in[5];
    const float* att2 = (const float*)d_in[6];
    const float* b2   = (const float*)d_in[7];
    const float* W3   = (const float*)d_in[8];
    const float* att3 = (const float*)d_in[9];
    const float* b3   = (const float*)d_in[10];
    float* out = (float*)d_out;

    const int TB = 256;
    const int warpGrid = (NN * 32 + TB - 1) / TB;
    const int gemmGrid = (NN + 63) / 64;

    // One-pass padded-CSR build (g_deg zeroed by previous call / load-time init)
    k_build<<<(EQ + NN + TB - 1) / TB, TB>>>(ei);

    // Layer 1: 128 -> 8x8
    k_gemm_wmma<128, 64, 8, false><<<gemmGrid, TB>>>(x, W1, att1);
    k_agg8<<<warpGrid, TB>>>(b1, 1);

    // Layer 2: 64 -> 8x8
    k_gemm_wmma<64, 64, 8, true><<<gemmGrid, TB>>>(nullptr, W2, att2);
    k_agg8<<<warpGrid, TB>>>(b2, 1);

    // Layer 3: 64 -> 1x32
    k_gemm_wmma<64, 32, 1, true><<<gemmGrid, TB>>>(nullptr, W3, att3);
    k_agg32<<<warpGrid, TB>>>(b3, out);
}

// round 14
// speedup vs baseline: 1.4780x; 1.4780x over previous
#include <cuda_runtime.h>
#include <cuda_fp16.h>
#include <mma.h>

using namespace nvcuda;

#define NN 100000
#define EE 1600000
#define EQ 400000   // EE/4
#define NB 98       // (NN + 1023) / 1024

// ---------------- scratch (static device globals; no allocation) ----------------
__device__ int    g_deg[NN];      // zero-init at load; re-zeroed by k_scan23 each call
__device__ int    g_rowptr[NN + 1];
__device__ int    g_cursor[NN];
__device__ int    g_bsum[128];
__device__ int    g_col[EE + NN];
__device__ __half g_h16[NN * 64];
__device__ __half g_act16[NN * 64];
__device__ float  g_adst[NN * 8];
__device__ float  g_asrc[NN * 8];

// dtype sniff: int64 indices in range -> is64 (8 loads from one cached line)
__device__ __forceinline__ int sniff64(const long long* p64) {
    int is64 = 1;
#pragma unroll
    for (int k = 0; k < 8; k++) {
        long long v = p64[k];
        if (v < 0 || v >= NN) is64 = 0;
    }
    return is64;
}

// ---------------- histogram: 4 edges/thread ----------------
__global__ void k_hist(const void* ei) {
    int t = blockIdx.x * blockDim.x + threadIdx.x;
    if (t >= EQ) return;
    const long long* p64 = (const long long*)ei;
    int is64 = sniff64(p64);
    int e0 = t * 4;
    int s[4], d[4];
    if (is64) {
#pragma unroll
        for (int j = 0; j < 4; j++) {
            s[j] = (int)p64[e0 + j];
            d[j] = (int)p64[EE + e0 + j];
        }
    } else {
        const int* p = (const int*)ei;
#pragma unroll
        for (int j = 0; j < 4; j++) {
            s[j] = p[e0 + j];
            d[j] = p[EE + e0 + j];
        }
    }
#pragma unroll
    for (int j = 0; j < 4; j++)
        if (s[j] != d[j]) atomicAdd(&g_deg[d[j]], 1);  // self-loops dropped (exp(-1e9-amax)==0)
}

// ---------------- scan (self-loop +1 folded in) ----------------
__global__ void k_scan1() {
    __shared__ int sh[1024];
    int tid = threadIdx.x;
    int i = blockIdx.x * 1024 + tid;
    int v = (i < NN) ? g_deg[i] + 1 : 0;  // +1 = appended self-loop
    sh[tid] = v;
    __syncthreads();
    for (int o = 1; o < 1024; o <<= 1) {
        int t = (tid >= o) ? sh[tid - o] : 0;
        __syncthreads();
        sh[tid] += t;
        __syncthreads();
    }
    if (i < NN) g_rowptr[i] = sh[tid] - v;
    if (tid == 1023) g_bsum[blockIdx.x] = sh[1023];
}

__global__ void k_scan23() {
    __shared__ int sh[128];
    int tid = threadIdx.x;
    int i = blockIdx.x * 256 + tid;
    if (tid < 128) sh[tid] = (tid < NB) ? g_bsum[tid] : 0;
    __syncthreads();
    for (int o = 1; o < 128; o <<= 1) {
        int t = (tid >= o && tid < 128) ? sh[tid - o] : 0;
        __syncthreads();
        if (tid < 128) sh[tid] += t;
        __syncthreads();
    }
    if (i < NN) {
        int blk = i >> 10;
        int exc = blk ? sh[blk - 1] : 0;
        int r = g_rowptr[i] + exc;
        g_rowptr[i] = r;
        g_cursor[i] = r;
        g_deg[i] = 0;  // reset for next call (deg fully consumed by scan1)
    }
    if (blockIdx.x == 0 && tid == 0) g_rowptr[NN] = sh[127];
}

// ---------------- scatter: 4 edges/thread, reads edge_index directly ----------------
__global__ void k_scatter(const void* ei) {
    int t = blockIdx.x * blockDim.x + threadIdx.x;
    if (t < EQ) {
        const long long* p64 = (const long long*)ei;
        int is64 = sniff64(p64);
        int e0 = t * 4;
        int s[4], d[4];
        if (is64) {
#pragma unroll
            for (int j = 0; j < 4; j++) {
                s[j] = (int)p64[e0 + j];
                d[j] = (int)p64[EE + e0 + j];
            }
        } else {
            const int* p = (const int*)ei;
#pragma unroll
            for (int j = 0; j < 4; j++) {
                s[j] = p[e0 + j];
                d[j] = p[EE + e0 + j];
            }
        }
        int pos[4];
#pragma unroll
        for (int j = 0; j < 4; j++)
            pos[j] = (s[j] != d[j]) ? atomicAdd(&g_cursor[d[j]], 1) : -1;
#pragma unroll
        for (int j = 0; j < 4; j++)
            if (pos[j] >= 0) g_col[pos[j]] = s[j];
    } else {
        int n = t - EQ;
        if (n < NN) {
            int p = atomicAdd(&g_cursor[n], 1);
            g_col[p] = n;  // appended self-loop
        }
    }
}

// ---------------- wmma tensor-core GEMM + fused attention-dot epilogue ----------------
// MR rows per block. 8 warps: MR/16 row bands x COLSPLIT = 128/MR column splits.
template <int K, int NOUT, int HEADS, bool HALF_A, int MR>
__global__ __launch_bounds__(256) void k_gemm_wmma(const float* __restrict__ Af,
                                                   const float* __restrict__ W,
                                                   const float* __restrict__ att) {
    constexpr int LDA = K + 8;
    constexpr int LDB = NOUT + 8;
    constexpr int LDC = NOUT + 8;
    constexpr int AB_BYTES = MR * LDA * 2 + K * LDB * 2;
    constexpr int C_BYTES = MR * LDC * 4;
    constexpr int SM_BYTES = AB_BYTES > C_BYTES ? AB_BYTES : C_BYTES;
    __shared__ __align__(16) char smem[SM_BYTES];
    __half (*Asm)[LDA] = reinterpret_cast<__half (*)[LDA]>(smem);
    __half (*Bsm)[LDB] = reinterpret_cast<__half (*)[LDB]>(smem + MR * LDA * 2);
    float  (*Csm)[LDC] = reinterpret_cast<float (*)[LDC]>(smem);

    int tid = threadIdx.x;
    int w = tid >> 5;
    int row0 = blockIdx.x * MR;

    for (int i = tid; i < K * NOUT / 4; i += 256) {
        int r = i / (NOUT / 4), c4 = i % (NOUT / 4);
        float4 v = ((const float4*)W)[i];
        __half2* dst = (__half2*)&Bsm[r][c4 * 4];
        dst[0] = __floats2half2_rn(v.x, v.y);
        dst[1] = __floats2half2_rn(v.z, v.w);
    }
    if (HALF_A) {
        for (int i = tid; i < MR * K / 8; i += 256) {
            int r = i / (K / 8), c8 = i % (K / 8);
            float4 v = make_float4(0.f, 0.f, 0.f, 0.f);
            if (row0 + r < NN)
                v = *(const float4*)&g_act16[(row0 + r) * K + c8 * 8];
            *(float4*)&Asm[r][c8 * 8] = v;
        }
    } else {
        for (int i = tid; i < MR * K / 4; i += 256) {
            int r = i / (K / 4), c4 = i % (K / 4);
            float4 v = make_float4(0.f, 0.f, 0.f, 0.f);
            if (row0 + r < NN)
                v = *(const float4*)&Af[(row0 + r) * K + c4 * 4];
            __half2* dst = (__half2*)&Asm[r][c4 * 4];
            dst[0] = __floats2half2_rn(v.x, v.y);
            dst[1] = __floats2half2_rn(v.z, v.w);
        }
    }
    __syncthreads();

    constexpr int COLSPLIT = 128 / MR;               // 2 for MR=64, 1 for MR=128
    constexpr int CFRAGS = NOUT / (16 * COLSPLIT);   // 2 / 4 / 2
    int rb = (w / COLSPLIT) * 16;
    int col0 = (w % COLSPLIT) * (NOUT / COLSPLIT);

    wmma::fragment<wmma::accumulator, 16, 16, 16, float> cfrag[CFRAGS];
#pragma unroll
    for (int j = 0; j < CFRAGS; j++) wmma::fill_fragment(cfrag[j], 0.f);

#pragma unroll
    for (int kk = 0; kk < K / 16; kk++) {
        wmma::fragment<wmma::matrix_a, 16, 16, 16, __half, wmma::row_major> afrag;
        wmma::load_matrix_sync(afrag, &Asm[rb][kk * 16], LDA);
#pragma unroll
        for (int j = 0; j < CFRAGS; j++) {
            wmma::fragment<wmma::matrix_b, 16, 16, 16, __half, wmma::row_major> bfrag;
            wmma::load_matrix_sync(bfrag, &Bsm[kk * 16][col0 + 16 * j], LDB);
            wmma::mma_sync(cfrag[j], afrag, bfrag, cfrag[j]);
        }
    }
    __syncthreads();
#pragma unroll
    for (int j = 0; j < CFRAGS; j++)
        wmma::store_matrix_sync(&Csm[rb][col0 + 16 * j], cfrag[j], LDC, wmma::mem_row_major);
    __syncthreads();

    for (int i = tid; i < MR * NOUT / 2; i += 256) {
        int r = i / (NOUT / 2), c2 = i % (NOUT / 2);
        if (row0 + r < NN)
            *(__half2*)&g_h16[(row0 + r) * NOUT + c2 * 2] =
                __floats2half2_rn(Csm[r][c2 * 2], Csm[r][c2 * 2 + 1]);
    }
    constexpr int CPH = NOUT / HEADS;
    for (int idx = tid; idx < MR * HEADS; idx += 256) {
        int r = idx / HEADS, h = idx % HEADS;
        float sd = 0.f, ss = 0.f;
#pragma unroll
        for (int c = 0; c < CPH; c++) {
            float v = Csm[r][h * CPH + c];
            sd += v * att[h * (2 * CPH) + c];
            ss += v * att[h * (2 * CPH) + CPH + c];
        }
        int row = row0 + r;
        if (row < NN) {
            g_adst[row * HEADS + h] = sd;
            g_asrc[row * HEADS + h] = ss;
        }
    }
}

__device__ __forceinline__ float leaky_exp(float a) {
    a = a > 0.f ? a : 0.2f * a;
    return __expf(a);
}

// ---------------- aggregate H=8: warp per node, 8-edge batches ----------------
__global__ __launch_bounds__(256) void k_agg8(const float* __restrict__ bias, int do_elu) {
    int t = blockIdx.x * blockDim.x + threadIdx.x;
    int n = t >> 5, lane = t & 31;
    if (n >= NN) return;
    const unsigned full = 0xffffffffu;
    int start = g_rowptr[n], end = g_rowptr[n + 1];
    int hA = lane & 7;
    int hB = lane >> 2;
    int eoff = lane >> 3;

    float adstA = g_adst[n * 8 + hA];
    float2 acc = make_float2(0.f, 0.f);
    float dsum = 0.f;

    for (int base = start; base < end; base += 8) {
        int eA = base + eoff;
        int eB = eA + 4;
        int validA = eA < end;
        int validB = eB < end;
        int ecA = validA ? eA : end - 1;
        int ecB = validB ? eB : end - 1;
        int sA = g_col[ecA];
        int sB = g_col[ecB];
        float aA = g_asrc[sA * 8 + hA];
        float aB = g_asrc[sB * 8 + hA];

        int s0 = __shfl_sync(full, sA, 0);
        int s1 = __shfl_sync(full, sA, 8);
        int s2 = __shfl_sync(full, sA, 16);
        int s3 = __shfl_sync(full, sA, 24);
        int s4 = __shfl_sync(full, sB, 0);
        int s5 = __shfl_sync(full, sB, 8);
        int s6 = __shfl_sync(full, sB, 16);
        int s7 = __shfl_sync(full, sB, 24);
        float2 v0 = __half22float2(*(const __half2*)&g_h16[s0 * 64 + lane * 2]);
        float2 v1 = __half22float2(*(const __half2*)&g_h16[s1 * 64 + lane * 2]);
        float2 v2 = __half22float2(*(const __half2*)&g_h16[s2 * 64 + lane * 2]);
        float2 v3 = __half22float2(*(const __half2*)&g_h16[s3 * 64 + lane * 2]);
        float2 v4 = __half22float2(*(const __half2*)&g_h16[s4 * 64 + lane * 2]);
        float2 v5 = __half22float2(*(const __half2*)&g_h16[s5 * 64 + lane * 2]);
        float2 v6 = __half22float2(*(const __half2*)&g_h16[s6 * 64 + lane * 2]);
        float2 v7 = __half22float2(*(const __half2*)&g_h16[s7 * 64 + lane * 2]);

        float exA = leaky_exp(adstA + aA);
        float exB = leaky_exp(adstA + aB);
        exA = validA ? exA : 0.f;
        exB = validB ? exB : 0.f;

        float w0 = __shfl_sync(full, exA, hB);
        float w1 = __shfl_sync(full, exA, 8 + hB);
        float w2 = __shfl_sync(full, exA, 16 + hB);
        float w3 = __shfl_sync(full, exA, 24 + hB);
        float w4 = __shfl_sync(full, exB, hB);
        float w5 = __shfl_sync(full, exB, 8 + hB);
        float w6 = __shfl_sync(full, exB, 16 + hB);
        float w7 = __shfl_sync(full, exB, 24 + hB);

        acc.x += v0.x * w0 + v1.x * w1 + v2.x * w2 + v3.x * w3;
        acc.x += v4.x * w4 + v5.x * w5 + v6.x * w6 + v7.x * w7;
        acc.y += v0.y * w0 + v1.y * w1 + v2.y * w2 + v3.y * w3;
        acc.y += v4.y * w4 + v5.y * w5 + v6.y * w6 + v7.y * w7;
        dsum += ((w0 + w1) + (w2 + w3)) + ((w4 + w5) + (w6 + w7));
    }
    float inv = 1.f / dsum;
    float o0 = acc.x * inv + bias[lane * 2];
    float o1 = acc.y * inv + bias[lane * 2 + 1];
    if (do_elu) {
        o0 = o0 > 0.f ? o0 : expm1f(o0);
        o1 = o1 > 0.f ? o1 : expm1f(o1);
    }
    *(__half2*)&g_act16[n * 64 + lane * 2] = __floats2half2_rn(o0, o1);
}

// ---------------- aggregate H=1: warp per node, 8-edge batches ----------------
__global__ __launch_bounds__(256) void k_agg32(const float* __restrict__ bias,
                                               float* __restrict__ outp) {
    int t = blockIdx.x * blockDim.x + threadIdx.x;
    int n = t >> 5, lane = t & 31;
    if (n >= NN) return;
    const unsigned full = 0xffffffffu;
    int start = g_rowptr[n], end = g_rowptr[n + 1];
    int half = lane >> 4;
    int c2 = (lane & 15) * 2;
    int eoff = lane & 7;

    float adst = g_adst[n];
    float2 acc = make_float2(0.f, 0.f);
    float dsum = 0.f;

    for (int base = start; base < end; base += 8) {
        int e = base + eoff;
        int valid = e < end;
        int ec = valid ? e : end - 1;
        int scol = g_col[ec];
        float ex = leaky_exp(adst + g_asrc[scol]);
        ex = valid ? ex : 0.f;

        int i0 = half, i1 = 2 + half, i2 = 4 + half, i3 = 6 + half;
        int s0 = __shfl_sync(full, scol, i0);
        int s1 = __shfl_sync(full, scol, i1);
        int s2 = __shfl_sync(full, scol, i2);
        int s3 = __shfl_sync(full, scol, i3);
        float2 v0 = __half22float2(*(const __half2*)&g_h16[s0 * 32 + c2]);
        float2 v1 = __half22float2(*(const __half2*)&g_h16[s1 * 32 + c2]);
        float2 v2 = __half22float2(*(const __half2*)&g_h16[s2 * 32 + c2]);
        float2 v3 = __half22float2(*(const __half2*)&g_h16[s3 * 32 + c2]);
        float w0 = __shfl_sync(full, ex, i0);
        float w1 = __shfl_sync(full, ex, i1);
        float w2 = __shfl_sync(full, ex, i2);
        float w3 = __shfl_sync(full, ex, i3);

        acc.x += v0.x * w0 + v1.x * w1 + v2.x * w2 + v3.x * w3;
        acc.y += v0.y * w0 + v1.y * w1 + v2.y * w2 + v3.y * w3;
        dsum += (w0 + w1) + (w2 + w3);
    }
    acc.x += __shfl_xor_sync(full, acc.x, 16);
    acc.y += __shfl_xor_sync(full, acc.y, 16);
    dsum += __shfl_xor_sync(full, dsum, 16);
    if (lane < 16) {
        float inv = 1.f / dsum;
        outp[n * 32 + c2] = acc.x * inv + bias[c2];
        outp[n * 32 + c2 + 1] = acc.y * inv + bias[c2 + 1];
    }
}

// ---------------- launch ----------------
extern "C" void kernel_launch(void* const* d_in, const int* in_sizes, int n_in,
                              void* d_out, int out_size) {
    const float* x    = (const float*)d_in[0];
    const void*  ei   = d_in[1];
    const float* W1   = (const float*)d_in[2];
    const float* att1 = (const float*)d_in[3];
    const float* b1   = (const float*)d_in[4];
    const float* W2   = (const float*)d_in[5];
    const float* att2 = (const float*)d_in[6];
    const float* b2   = (const float*)d_in[7];
    const float* W3   = (const float*)d_in[8];
    const float* att3 = (const float*)d_in[9];
    const float* b3   = (const float*)d_in[10];
    float* out = (float*)d_out;

    const int TB = 256;
    const int warpGrid = (NN * 32 + TB - 1) / TB;

    // CSR build (dst layer-invariant); g_deg zeroed by previous call / load-time init
    k_hist<<<(EQ + TB - 1) / TB, TB>>>(ei);
    k_scan1<<<NB, 1024>>>();
    k_scan23<<<(NN + 255) / 256, 256>>>();
    k_scatter<<<(EQ + NN + TB - 1) / TB, TB>>>(ei);

    // Layer 1: 128 -> 8x8 (64-row tiles; K=128 A-tile too big for 128 rows)
    k_gemm_wmma<128, 64, 8, false, 64><<<(NN + 63) / 64, TB>>>(x, W1, att1);
    k_agg8<<<warpGrid, TB>>>(b1, 1);

    // Layer 2: 64 -> 8x8 (128-row tiles)
    k_gemm_wmma<64, 64, 8, true, 128><<<(NN + 127) / 128, TB>>>(nullptr, W2, att2);
    k_agg8<<<warpGrid, TB>>>(b2, 1);

    // Layer 3: 64 -> 1x32 (128-row tiles)
    k_gemm_wmma<64, 32, 1, true, 128><<<(NN + 127) / 128, TB>>>(nullptr, W3, att3);
    k_agg32<<<warpGrid, TB>>>(b3, out);
}